// round 2
// baseline (speedup 1.0000x reference)
#include <cuda_runtime.h>

// Problem constants
#define B_    16
#define C_    256
#define H_    64
#define W_    64
#define HW_   4096
#define NH_   8
#define E_    32
#define NWIN_ 8

// Scratch (device globals — no allocation allowed)
__device__ float g_Q[B_ * C_ * HW_];
__device__ float g_K[B_ * C_ * HW_];
__device__ float g_V[B_ * C_ * HW_];
__device__ float g_att[B_ * C_ * HW_];

// ---------------------------------------------------------------------------
// Kernel 1: QKV GEMM.  out[n, hw] = sum_k W1[n,k] * x[b,k,hw] + b1[n]
// n in [0,768): n%3 selects Q/K/V, n/3 is the channel.
// Tile: 64 n-rows x 64 hw-cols, k-tile 32. 256 threads, 4x4 micro-tile.
// ---------------------------------------------------------------------------
__global__ __launch_bounds__(256) void qkv_gemm(const float* __restrict__ x,
                                                const float* __restrict__ W1,
                                                const float* __restrict__ b1) {
    __shared__ float As[64][33];  // W1 tile [n][k]
    __shared__ float Bs[32][64];  // x tile  [k][hw]
    const int b  = blockIdx.z;
    const int n0 = blockIdx.y * 64;
    const int m0 = blockIdx.x * 64;
    const int tid = threadIdx.x;
    const int tx = tid & 15, ty = tid >> 4;

    float acc[4][4] = {};
    for (int k0 = 0; k0 < 256; k0 += 32) {
#pragma unroll
        for (int l = 0; l < 8; l++) {
            int idx = tid + l * 256;        // 2048 elements
            int i = idx >> 5, j = idx & 31;
            As[i][j] = W1[(n0 + i) * 256 + k0 + j];
        }
#pragma unroll
        for (int l = 0; l < 8; l++) {
            int idx = tid + l * 256;
            int j = idx >> 6, i = idx & 63;
            Bs[j][i] = x[(b * 256 + k0 + j) * HW_ + m0 + i];
        }
        __syncthreads();
#pragma unroll
        for (int kk = 0; kk < 32; kk++) {
            float a[4];
#pragma unroll
            for (int i2 = 0; i2 < 4; i2++) a[i2] = As[ty * 4 + i2][kk];
            float4 b4 = *reinterpret_cast<const float4*>(&Bs[kk][tx * 4]);
            float bb[4] = {b4.x, b4.y, b4.z, b4.w};
#pragma unroll
            for (int i2 = 0; i2 < 4; i2++)
#pragma unroll
                for (int j2 = 0; j2 < 4; j2++)
                    acc[i2][j2] += a[i2] * bb[j2];
        }
        __syncthreads();
    }

#pragma unroll
    for (int i2 = 0; i2 < 4; i2++) {
        int n = n0 + ty * 4 + i2;
        float bias = b1[n];
        int type = n % 3, c = n / 3;
        float* dst = (type == 0) ? g_Q : ((type == 1) ? g_K : g_V);
#pragma unroll
        for (int j2 = 0; j2 < 4; j2++)
            dst[(b * 256 + c) * HW_ + m0 + tx * 4 + j2] = acc[i2][j2] + bias;
    }
}

// ---------------------------------------------------------------------------
// Kernel 2: windowed attention. One block per (b, head, window).
// Q: 64 positions x 32, K/V: 144 positions (12x12 overlapping, pad 2) x 32.
// ---------------------------------------------------------------------------
__global__ __launch_bounds__(256) void attn_kernel() {
    extern __shared__ float sm[];
    float* Qs   = sm;                 // [64][33]
    float* Ks   = Qs + 64 * 33;      // [144][33]
    float* Vs   = Ks + 144 * 33;     // [144][33]
    float* Ps   = Vs + 144 * 33;     // [64][145]
    float* isum = Ps + 64 * 145;     // [64]

    const int win  = blockIdx.x;
    const int wi   = win >> 3, wj = win & 7;
    const int head = blockIdx.y;
    const int b    = blockIdx.z;
    const int tid  = threadIdx.x;
    const int bc   = b * 256 + head * 32;

    // ---- Load Q (64x32)
#pragma unroll
    for (int l = 0; l < 8; l++) {
        int idx = tid + l * 256;        // 2048
        int e = idx >> 6, p = idx & 63;
        int hw = (wi * 8 + (p >> 3)) * 64 + wj * 8 + (p & 7);
        Qs[p * 33 + e] = g_Q[(bc + e) * HW_ + hw];
    }
    // ---- Load K, V (144x32) with implicit zero-padding
    for (int idx = tid; idx < 144 * 32; idx += 256) {
        int e = idx / 144, k = idx % 144;
        int pr = k / 12, pc = k % 12;
        int gh = wi * 8 + pr - 2, gw = wj * 8 + pc - 2;
        float kv = 0.f, vv = 0.f;
        if ((unsigned)gh < 64u && (unsigned)gw < 64u) {
            int off = (bc + e) * HW_ + gh * 64 + gw;
            kv = g_K[off];
            vv = g_V[off];
        }
        Ks[k * 33 + e] = kv;
        Vs[k * 33 + e] = vv;
    }
    __syncthreads();

    // ---- Scores: S[q][k] = scale * dot(Q[q], K[k])
    // Register blocking: each thread does q in {qp, qp+32}, k in kg+{0,36,72,108}
    const float scale = 0.17677669529663687f;  // 1/sqrt(32)
#pragma unroll
    for (int l = 0; l < 5; l++) {
        int g = tid + l * 256;
        if (g < 1152) {                        // 32 qp * 36 kg
            int qp = g / 36, kg = g % 36;
            float a00 = 0, a01 = 0, a02 = 0, a03 = 0;
            float a10 = 0, a11 = 0, a12 = 0, a13 = 0;
#pragma unroll
            for (int e = 0; e < 32; e++) {
                float q0 = Qs[qp * 33 + e];
                float q1 = Qs[(qp + 32) * 33 + e];
                float k0 = Ks[(kg      ) * 33 + e];
                float k1 = Ks[(kg +  36) * 33 + e];
                float k2 = Ks[(kg +  72) * 33 + e];
                float k3 = Ks[(kg + 108) * 33 + e];
                a00 += q0 * k0; a01 += q0 * k1; a02 += q0 * k2; a03 += q0 * k3;
                a10 += q1 * k0; a11 += q1 * k1; a12 += q1 * k2; a13 += q1 * k3;
            }
            Ps[qp * 145 + kg      ] = a00 * scale;
            Ps[qp * 145 + kg +  36] = a01 * scale;
            Ps[qp * 145 + kg +  72] = a02 * scale;
            Ps[qp * 145 + kg + 108] = a03 * scale;
            Ps[(qp + 32) * 145 + kg      ] = a10 * scale;
            Ps[(qp + 32) * 145 + kg +  36] = a11 * scale;
            Ps[(qp + 32) * 145 + kg +  72] = a12 * scale;
            Ps[(qp + 32) * 145 + kg + 108] = a13 * scale;
        }
    }
    __syncthreads();

    // ---- Softmax over 144 keys; warp w handles rows w*8 .. w*8+7
    {
        const int warp = tid >> 5, lane = tid & 31;
        for (int r = 0; r < 8; r++) {
            int q = warp * 8 + r;
            float m = -1e30f;
            for (int k = lane; k < 144; k += 32) m = fmaxf(m, Ps[q * 145 + k]);
#pragma unroll
            for (int o = 16; o > 0; o >>= 1) m = fmaxf(m, __shfl_xor_sync(0xffffffffu, m, o));
            float s = 0.f;
            for (int k = lane; k < 144; k += 32) {
                float ev = __expf(Ps[q * 145 + k] - m);
                Ps[q * 145 + k] = ev;
                s += ev;
            }
#pragma unroll
            for (int o = 16; o > 0; o >>= 1) s += __shfl_xor_sync(0xffffffffu, s, o);
            if (lane == 0) isum[q] = 1.0f / s;
        }
    }
    __syncthreads();

    // ---- AV: out[q][e] = (sum_k P[q][k] * V[k][e]) * isum[q]
    // Each thread: q in {qp, qp+32}, e in eg*4 .. eg*4+3
    {
        int qp = tid & 31, eg = tid >> 5;
        float acc[2][4] = {};
#pragma unroll 4
        for (int k = 0; k < 144; k++) {
            float p0 = Ps[qp * 145 + k];
            float p1 = Ps[(qp + 32) * 145 + k];
#pragma unroll
            for (int ee = 0; ee < 4; ee++) {
                float v = Vs[k * 33 + eg * 4 + ee];
                acc[0][ee] += p0 * v;
                acc[1][ee] += p1 * v;
            }
        }
        float i0 = isum[qp], i1 = isum[qp + 32];
        int hw0 = (wi * 8 + (qp >> 3)) * 64 + wj * 8 + (qp & 7);
        int q1 = qp + 32;
        int hw1 = (wi * 8 + (q1 >> 3)) * 64 + wj * 8 + (q1 & 7);
#pragma unroll
        for (int ee = 0; ee < 4; ee++) {
            g_att[(bc + eg * 4 + ee) * HW_ + hw0] = acc[0][ee] * i0;
            g_att[(bc + eg * 4 + ee) * HW_ + hw1] = acc[1][ee] * i1;
        }
    }
}

// ---------------------------------------------------------------------------
// Kernel 3: output GEMM.  y[b,n,hw] = sum_c W2[n,c] * att[b,c,hw] + b2[n]
// ---------------------------------------------------------------------------
__global__ __launch_bounds__(256) void out_gemm(const float* __restrict__ W2,
                                                const float* __restrict__ b2,
                                                float* __restrict__ y) {
    __shared__ float As[64][33];
    __shared__ float Bs[32][64];
    const int b  = blockIdx.z;
    const int n0 = blockIdx.y * 64;
    const int m0 = blockIdx.x * 64;
    const int tid = threadIdx.x;
    const int tx = tid & 15, ty = tid >> 4;

    float acc[4][4] = {};
    for (int k0 = 0; k0 < 256; k0 += 32) {
#pragma unroll
        for (int l = 0; l < 8; l++) {
            int idx = tid + l * 256;
            int i = idx >> 5, j = idx & 31;
            As[i][j] = W2[(n0 + i) * 256 + k0 + j];
        }
#pragma unroll
        for (int l = 0; l < 8; l++) {
            int idx = tid + l * 256;
            int j = idx >> 6, i = idx & 63;
            Bs[j][i] = g_att[(b * 256 + k0 + j) * HW_ + m0 + i];
        }
        __syncthreads();
#pragma unroll
        for (int kk = 0; kk < 32; kk++) {
            float a[4];
#pragma unroll
            for (int i2 = 0; i2 < 4; i2++) a[i2] = As[ty * 4 + i2][kk];
            float4 b4 = *reinterpret_cast<const float4*>(&Bs[kk][tx * 4]);
            float bb[4] = {b4.x, b4.y, b4.z, b4.w};
#pragma unroll
            for (int i2 = 0; i2 < 4; i2++)
#pragma unroll
                for (int j2 = 0; j2 < 4; j2++)
                    acc[i2][j2] += a[i2] * bb[j2];
        }
        __syncthreads();
    }

#pragma unroll
    for (int i2 = 0; i2 < 4; i2++) {
        int n = n0 + ty * 4 + i2;
        float bias = b2[n];
#pragma unroll
        for (int j2 = 0; j2 < 4; j2++)
            y[(b * 256 + n) * HW_ + m0 + tx * 4 + j2] = acc[i2][j2] + bias;
    }
}

// ---------------------------------------------------------------------------
extern "C" void kernel_launch(void* const* d_in, const int* in_sizes, int n_in,
                              void* d_out, int out_size) {
    const float* x  = (const float*)d_in[0];
    const float* W1 = (const float*)d_in[1];
    const float* b1 = (const float*)d_in[2];
    const float* W2 = (const float*)d_in[3];
    const float* b2 = (const float*)d_in[4];
    float* y = (float*)d_out;

    // Stage 1: QKV projection
    qkv_gemm<<<dim3(HW_ / 64, 768 / 64, B_), 256>>>(x, W1, b1);

    // Stage 2: overlapping windowed attention
    const size_t attn_smem = (size_t)(64 * 33 + 144 * 33 * 2 + 64 * 145 + 64) * sizeof(float);
    cudaFuncSetAttribute(attn_kernel, cudaFuncAttributeMaxDynamicSharedMemorySize,
                         (int)attn_smem);
    attn_kernel<<<dim3(NWIN_ * NWIN_, NH_, B_), 256, attn_smem>>>();

    // Stage 3: output projection
    out_gemm<<<dim3(HW_ / 64, 256 / 64, B_), 256>>>(W2, b2, y);
}

// round 4
// speedup vs baseline: 1.2746x; 1.2746x over previous
#include <cuda_runtime.h>

#define B_    16
#define C_    256
#define HW_   4096
#define NH_   8
#define NWIN_ 8

typedef unsigned long long u64;

__device__ float g_Q[B_ * C_ * HW_];
__device__ float g_K[B_ * C_ * HW_];
__device__ float g_V[B_ * C_ * HW_];
__device__ float g_att[B_ * C_ * HW_];

__device__ __forceinline__ u64 pack2(float x) {
    u64 r;
    asm("mov.b64 %0, {%1, %1};" : "=l"(r) : "f"(x));
    return r;
}
__device__ __forceinline__ void fma2(u64& acc, u64 a, u64 b) {
    asm("fma.rn.f32x2 %0, %1, %2, %0;" : "+l"(acc) : "l"(a), "l"(b));
}
__device__ __forceinline__ float2 unpack2(u64 v) {
    float2 f;
    asm("mov.b64 {%0, %1}, %2;" : "=f"(f.x), "=f"(f.y) : "l"(v));
    return f;
}

// ---------------------------------------------------------------------------
// GEMM: out[b, n, hw] = sum_k Wt[n,k] * src[b,k,hw] + bias[n]
// WHICH==0: src = X arg, N=768, scatter into g_Q/g_K/g_V by n%3.
// WHICH==1: src = g_att (device symbol, resolved IN DEVICE CODE), N=256 -> Y.
// Tile 128n x 128hw, kt=16, 256 threads, 8x8 micro-tile, packed f32x2 math.
// ---------------------------------------------------------------------------
template <int WHICH>
__global__ __launch_bounds__(256) void gemm_kernel(const float* __restrict__ Wt,
                                                   const float* __restrict__ bias,
                                                   const float* __restrict__ X,
                                                   float* __restrict__ Y) {
    __shared__ float As[16][132];   // [k][n] transposed weight tile
    __shared__ float Bs[16][128];   // [k][hw]

    // Resolve the activation source in device code (g_att is a device symbol;
    // its address must NOT be taken from host code).
    const float* __restrict__ src = (WHICH == 0) ? X : (const float*)g_att;

    const int b   = blockIdx.z;
    const int n0  = blockIdx.y * 128;
    const int m0  = blockIdx.x * 128;
    const int tid = threadIdx.x;
    const int tx  = tid & 15;       // hw group (8 cols)
    const int ty  = tid >> 4;       // n  group (8 rows)

    const int aN = tid >> 2;              // 0..63 (second chunk +64)
    const int aJ = (tid & 3) * 4;         // k sub-offset
    const int bK = tid >> 5;              // 0..7  (second chunk +8)
    const int bC = (tid & 31) * 4;        // hw sub-offset

    const float* Arow0 = Wt + (n0 + aN) * 256 + aJ;
    const float* Arow1 = Wt + (n0 + aN + 64) * 256 + aJ;
    const float* Xrow0 = src + (b * 256 + bK) * HW_ + m0 + bC;
    const float* Xrow1 = src + (b * 256 + bK + 8) * HW_ + m0 + bC;

    u64 acc[8][4];
#pragma unroll
    for (int i = 0; i < 8; i++)
#pragma unroll
        for (int j = 0; j < 4; j++) acc[i][j] = 0ull;

    float4 pa0 = *(const float4*)(Arow0);
    float4 pa1 = *(const float4*)(Arow1);
    float4 pb0 = *(const float4*)(Xrow0);
    float4 pb1 = *(const float4*)(Xrow1);

    for (int k0 = 0; k0 < 256; k0 += 16) {
        As[aJ + 0][aN] = pa0.x;  As[aJ + 1][aN] = pa0.y;
        As[aJ + 2][aN] = pa0.z;  As[aJ + 3][aN] = pa0.w;
        As[aJ + 0][aN + 64] = pa1.x;  As[aJ + 1][aN + 64] = pa1.y;
        As[aJ + 2][aN + 64] = pa1.z;  As[aJ + 3][aN + 64] = pa1.w;
        *(float4*)&Bs[bK][bC]     = pb0;
        *(float4*)&Bs[bK + 8][bC] = pb1;
        __syncthreads();

        if (k0 + 16 < 256) {
            pa0 = *(const float4*)(Arow0 + k0 + 16);
            pa1 = *(const float4*)(Arow1 + k0 + 16);
            pb0 = *(const float4*)(Xrow0 + (k0 + 16) * HW_);
            pb1 = *(const float4*)(Xrow1 + (k0 + 16) * HW_);
        }

#pragma unroll
        for (int kk = 0; kk < 16; kk++) {
            const float4 av0 = *(const float4*)&As[kk][ty * 8];
            const float4 av1 = *(const float4*)&As[kk][ty * 8 + 4];
            const ulonglong2 bl0 = *(const ulonglong2*)&Bs[kk][tx * 8];
            const ulonglong2 bl1 = *(const ulonglong2*)&Bs[kk][tx * 8 + 4];
            u64 bp[4] = {bl0.x, bl0.y, bl1.x, bl1.y};
            float a[8] = {av0.x, av0.y, av0.z, av0.w, av1.x, av1.y, av1.z, av1.w};
#pragma unroll
            for (int i = 0; i < 8; i++) {
                u64 ap = pack2(a[i]);
#pragma unroll
                for (int j = 0; j < 4; j++) fma2(acc[i][j], ap, bp[j]);
            }
        }
        __syncthreads();
    }

    // epilogue
#pragma unroll
    for (int i = 0; i < 8; i++) {
        const int n = n0 + ty * 8 + i;
        const float bv = bias[n];
        float o[8];
#pragma unroll
        for (int j = 0; j < 4; j++) {
            float2 v = unpack2(acc[i][j]);
            o[j * 2]     = v.x + bv;
            o[j * 2 + 1] = v.y + bv;
        }
        float* dst;
        if (WHICH == 0) {
            const int type = n % 3, c = n / 3;
            float* base = (type == 0) ? g_Q : ((type == 1) ? g_K : g_V);
            dst = base + (b * 256 + c) * HW_ + m0 + tx * 8;
        } else {
            dst = Y + (b * 256 + n) * HW_ + m0 + tx * 8;
        }
        *(float4*)(dst)     = make_float4(o[0], o[1], o[2], o[3]);
        *(float4*)(dst + 4) = make_float4(o[4], o[5], o[6], o[7]);
    }
}

// ---------------------------------------------------------------------------
// Attention: one block per (b, head, window). 256 threads.
// Q 64x32 (pre-scaled), K/V 144x32 (12x12 overlap, pad 2), packed f32x2 math.
// ---------------------------------------------------------------------------
__global__ __launch_bounds__(256) void attn_kernel() {
    extern __shared__ float sm[];
    float* Qs   = sm;                  // [64][34]
    float* Ks   = Qs + 64 * 34;        // [144][34]
    float* Vs   = Ks + 144 * 34;       // [144][34]
    float* Ps   = Vs + 144 * 34;       // [64][146]
    float* isum = Ps + 64 * 146;       // [64]
    float* scratch = Qs;               // reused after scores (2176 >= 2048 floats)

    const int win  = blockIdx.x;
    const int wi   = win >> 3, wj = win & 7;
    const int head = blockIdx.y;
    const int b    = blockIdx.z;
    const int tid  = threadIdx.x;
    const int bc   = b * 256 + head * 32;
    const float scale = 0.17677669529663687f;   // 1/sqrt(32)

    // ---- Load Q (scaled)
#pragma unroll
    for (int l = 0; l < 8; l++) {
        int idx = tid + l * 256;
        int e = idx >> 6, p = idx & 63;
        int hw = (wi * 8 + (p >> 3)) * 64 + wj * 8 + (p & 7);
        Qs[p * 34 + e] = g_Q[(bc + e) * HW_ + hw] * scale;
    }
    // ---- Load K, V with zero pad
    for (int idx = tid; idx < 144 * 32; idx += 256) {
        int e = idx / 144, k = idx - e * 144;
        int pr = k / 12, pc = k - pr * 12;
        int gh = wi * 8 + pr - 2, gw = wj * 8 + pc - 2;
        float kv = 0.f, vv = 0.f;
        if ((unsigned)gh < 64u && (unsigned)gw < 64u) {
            int off = (bc + e) * HW_ + gh * 64 + gw;
            kv = g_K[off];
            vv = g_V[off];
        }
        Ks[k * 34 + e] = kv;
        Vs[k * 34 + e] = vv;
    }
    __syncthreads();

    // ---- Scores: thread (qg,kg) does q = qg*4+i, k = kg*9+j, packed over e
    {
        const int qg = tid >> 4, kg = tid & 15;
        const float* qbase = Qs + qg * 4 * 34;
        const float* kbase = Ks + kg * 9 * 34;
        u64 acc[4][9];
#pragma unroll
        for (int i = 0; i < 4; i++)
#pragma unroll
            for (int j = 0; j < 9; j++) acc[i][j] = 0ull;

#pragma unroll
        for (int e2 = 0; e2 < 16; e2++) {
            u64 kp[9];
#pragma unroll
            for (int j = 0; j < 9; j++)
                kp[j] = *(const u64*)(kbase + j * 34 + e2 * 2);
#pragma unroll
            for (int i = 0; i < 4; i++) {
                u64 qp = *(const u64*)(qbase + i * 34 + e2 * 2);
#pragma unroll
                for (int j = 0; j < 9; j++) fma2(acc[i][j], qp, kp[j]);
            }
        }
#pragma unroll
        for (int i = 0; i < 4; i++)
#pragma unroll
            for (int j = 0; j < 9; j++) {
                float2 v = unpack2(acc[i][j]);
                Ps[(qg * 4 + i) * 146 + kg * 9 + j] = v.x + v.y;
            }
    }
    __syncthreads();

    // ---- Softmax over 144 keys; warp w handles rows w*8..w*8+7
    {
        const int warp = tid >> 5, lane = tid & 31;
        for (int r = 0; r < 8; r++) {
            int q = warp * 8 + r;
            float m = -1e30f;
            for (int k = lane; k < 144; k += 32) m = fmaxf(m, Ps[q * 146 + k]);
#pragma unroll
            for (int o = 16; o > 0; o >>= 1) m = fmaxf(m, __shfl_xor_sync(0xffffffffu, m, o));
            float s = 0.f;
            for (int k = lane; k < 144; k += 32) {
                float ev = __expf(Ps[q * 146 + k] - m);
                Ps[q * 146 + k] = ev;
                s += ev;
            }
#pragma unroll
            for (int o = 16; o > 0; o >>= 1) s += __shfl_xor_sync(0xffffffffu, s, o);
            if (lane == 0) isum[q] = 1.0f / s;
        }
    }
    __syncthreads();

    // ---- AV: thread (kh, eg, qp) does q in {qp, qp+32}, e = eg*8..+7,
    //          k in [kh*72, kh*72+72). Packed over e. Combine halves via smem.
    const int kh = tid >> 7;
    const int eg = (tid >> 5) & 3;
    const int qp = tid & 31;
    {
        u64 vacc[2][4];
#pragma unroll
        for (int c = 0; c < 4; c++) { vacc[0][c] = 0ull; vacc[1][c] = 0ull; }
        const int kend = kh * 72 + 72;
#pragma unroll 4
        for (int k = kh * 72; k < kend; k++) {
            u64 p0 = pack2(Ps[qp * 146 + k]);
            u64 p1 = pack2(Ps[(qp + 32) * 146 + k]);
            const u64* vrow = (const u64*)(Vs + k * 34 + eg * 8);
#pragma unroll
            for (int c = 0; c < 4; c++) {
                u64 v = vrow[c];
                fma2(vacc[0][c], p0, v);
                fma2(vacc[1][c], p1, v);
            }
        }
        if (kh == 0) {
#pragma unroll
            for (int c = 0; c < 4; c++) {
                float2 v0 = unpack2(vacc[0][c]);
                float2 v1 = unpack2(vacc[1][c]);
                scratch[qp * 32 + eg * 8 + 2 * c]            = v0.x;
                scratch[qp * 32 + eg * 8 + 2 * c + 1]        = v0.y;
                scratch[(qp + 32) * 32 + eg * 8 + 2 * c]     = v1.x;
                scratch[(qp + 32) * 32 + eg * 8 + 2 * c + 1] = v1.y;
            }
        }
        __syncthreads();
        if (kh == 1) {
            const float i0 = isum[qp], i1 = isum[qp + 32];
            const int hw0 = (wi * 8 + (qp >> 3)) * 64 + wj * 8 + (qp & 7);
            const int q1 = qp + 32;
            const int hw1 = (wi * 8 + (q1 >> 3)) * 64 + wj * 8 + (q1 & 7);
#pragma unroll
            for (int c = 0; c < 4; c++) {
                float2 v0 = unpack2(vacc[0][c]);
                float2 v1 = unpack2(vacc[1][c]);
                int e = eg * 8 + 2 * c;
                float a0 = (v0.x + scratch[qp * 32 + e])     * i0;
                float b0 = (v0.y + scratch[qp * 32 + e + 1]) * i0;
                float a1 = (v1.x + scratch[q1 * 32 + e])     * i1;
                float b1 = (v1.y + scratch[q1 * 32 + e + 1]) * i1;
                g_att[(bc + e) * HW_ + hw0]     = a0;
                g_att[(bc + e + 1) * HW_ + hw0] = b0;
                g_att[(bc + e) * HW_ + hw1]     = a1;
                g_att[(bc + e + 1) * HW_ + hw1] = b1;
            }
        }
    }
}

// ---------------------------------------------------------------------------
extern "C" void kernel_launch(void* const* d_in, const int* in_sizes, int n_in,
                              void* d_out, int out_size) {
    const float* x  = (const float*)d_in[0];
    const float* W1 = (const float*)d_in[1];
    const float* b1 = (const float*)d_in[2];
    const float* W2 = (const float*)d_in[3];
    const float* b2 = (const float*)d_in[4];
    float* y = (float*)d_out;

    gemm_kernel<0><<<dim3(HW_ / 128, 768 / 128, B_), 256>>>(W1, b1, x, nullptr);

    const size_t attn_smem =
        (size_t)(64 * 34 + 144 * 34 * 2 + 64 * 146 + 64) * sizeof(float);
    cudaFuncSetAttribute(attn_kernel, cudaFuncAttributeMaxDynamicSharedMemorySize,
                         (int)attn_smem);
    attn_kernel<<<dim3(NWIN_ * NWIN_, NH_, B_), 256, attn_smem>>>();

    gemm_kernel<1><<<dim3(HW_ / 128, 256 / 128, B_), 256>>>(W2, b2, nullptr, y);
}

// round 6
// speedup vs baseline: 1.5452x; 1.2123x over previous
#include <cuda_runtime.h>
#include <cstdint>

#define B_    16
#define C_    256
#define HW_   4096
#define NH_   8
#define NWIN_ 8

typedef unsigned long long u64;

__device__ float g_Q[B_ * C_ * HW_];
__device__ float g_K[B_ * C_ * HW_];
__device__ float g_V[B_ * C_ * HW_];
__device__ float g_att[B_ * C_ * HW_];

__device__ __forceinline__ uint32_t to_tf32_u(float x) {
    uint32_t u;
    asm("cvt.rna.tf32.f32 %0, %1;" : "=r"(u) : "f"(x));
    return u;
}
__device__ __forceinline__ void mma_tf32(float* d, const uint32_t* a, const uint32_t* b) {
    asm volatile(
        "mma.sync.aligned.m16n8k8.row.col.f32.tf32.tf32.f32 "
        "{%0,%1,%2,%3}, {%4,%5,%6,%7}, {%8,%9}, {%0,%1,%2,%3};"
        : "+f"(d[0]), "+f"(d[1]), "+f"(d[2]), "+f"(d[3])
        : "r"(a[0]), "r"(a[1]), "r"(a[2]), "r"(a[3]), "r"(b[0]), "r"(b[1]));
}

// ===========================================================================
// Tensor-core GEMM (mma.sync tf32):
//   out[b, n, hw] = sum_k Wt[n,k] * src[b,k,hw] + bias[n]
// WHICH==0: src = X, N=768, scatter into g_Q/g_K/g_V by n%3.
// WHICH==1: src = g_att, N=256 -> Y.
// Block tile 128n x 128hw, k-chunks of 32, double-buffered smem.
// 8 warps = 4(n) x 2(hw); warp tile 32n x 64hw = 2 x 8 m16n8k8 frags.
// ===========================================================================
#define SSTRIDE 36
#define STAGE_FLOATS (2 * 128 * SSTRIDE)   // sA + sB per stage

template <int WHICH>
__global__ __launch_bounds__(256, 1) void gemm_mma(const float* __restrict__ Wt,
                                                   const float* __restrict__ bias,
                                                   const float* __restrict__ X,
                                                   float* __restrict__ Y) {
    extern __shared__ uint32_t smem[];   // tf32 bit patterns

    const float* __restrict__ src = (WHICH == 0) ? X : (const float*)g_att;
    const int b   = blockIdx.z;
    const int n0  = blockIdx.y * 128;
    const int m0  = blockIdx.x * 128;
    const int tid = threadIdx.x;
    const int wid = tid >> 5, lane = tid & 31;
    const int qr  = lane >> 2, qc = lane & 3;

    const int warp_n  = (wid & 3) * 32;
    const int warp_hw = (wid >> 2) * 64;

    // A-load mapping: n_a = tid>>1 (0..127), k_a = (tid&1)*16
    const int n_a = tid >> 1;
    const int k_a = (tid & 1) * 16;
    // B-load mapping: k_b = tid&31 (0..31), hw_b = (tid>>5)*16
    const int k_b  = tid & 31;
    const int hw_b = (tid >> 5) * 16;

    const float* Ag = Wt + (size_t)(n0 + n_a) * 256 + k_a;
    const float* Bg = src + (size_t)(b * 256 + k_b) * HW_ + m0 + hw_b;

    float d[2][8][4];
#pragma unroll
    for (int i = 0; i < 2; i++)
#pragma unroll
        for (int j = 0; j < 8; j++)
#pragma unroll
            for (int l = 0; l < 4; l++) d[i][j][l] = 0.f;

    float4 pa[4], pb[4];
#pragma unroll
    for (int j = 0; j < 4; j++) {
        pa[j] = *(const float4*)(Ag + j * 4);
        pb[j] = *(const float4*)(Bg + j * 4);
    }

    for (int c = 0; c < 8; c++) {
        uint32_t* sA = smem + (c & 1) * STAGE_FLOATS;
        uint32_t* sB = sA + 128 * SSTRIDE;

        // commit prefetched chunk (convert to tf32)
#pragma unroll
        for (int j = 0; j < 4; j++) {
            uint4 v = make_uint4(to_tf32_u(pa[j].x), to_tf32_u(pa[j].y),
                                 to_tf32_u(pa[j].z), to_tf32_u(pa[j].w));
            sA[n_a * SSTRIDE + k_a + j * 4 + 0] = v.x;
            sA[n_a * SSTRIDE + k_a + j * 4 + 1] = v.y;
            sA[n_a * SSTRIDE + k_a + j * 4 + 2] = v.z;
            sA[n_a * SSTRIDE + k_a + j * 4 + 3] = v.w;
        }
#pragma unroll
        for (int j = 0; j < 4; j++) {
            sB[(hw_b + j * 4 + 0) * SSTRIDE + k_b] = to_tf32_u(pb[j].x);
            sB[(hw_b + j * 4 + 1) * SSTRIDE + k_b] = to_tf32_u(pb[j].y);
            sB[(hw_b + j * 4 + 2) * SSTRIDE + k_b] = to_tf32_u(pb[j].z);
            sB[(hw_b + j * 4 + 3) * SSTRIDE + k_b] = to_tf32_u(pb[j].w);
        }
        __syncthreads();

        if (c < 7) {
            const int k0n = (c + 1) * 32;
#pragma unroll
            for (int j = 0; j < 4; j++) {
                pa[j] = *(const float4*)(Ag + k0n + j * 4);
                pb[j] = *(const float4*)(Bg + (size_t)k0n * HW_ + j * 4);
            }
        }

        // 4 k8-steps of mma over this chunk
#pragma unroll
        for (int ks = 0; ks < 4; ks++) {
            const int k0s = ks * 8;
            uint32_t af[2][4], bf[8][2];
#pragma unroll
            for (int fm = 0; fm < 2; fm++) {
                const uint32_t* ap = sA + (warp_n + fm * 16 + qr) * SSTRIDE + k0s + qc;
                af[fm][0] = ap[0];
                af[fm][1] = ap[8 * SSTRIDE];
                af[fm][2] = ap[4];
                af[fm][3] = ap[8 * SSTRIDE + 4];
            }
#pragma unroll
            for (int fn = 0; fn < 8; fn++) {
                const uint32_t* bp = sB + (warp_hw + fn * 8 + qr) * SSTRIDE + k0s + qc;
                bf[fn][0] = bp[0];
                bf[fn][1] = bp[4];
            }
#pragma unroll
            for (int fm = 0; fm < 2; fm++)
#pragma unroll
                for (int fn = 0; fn < 8; fn++)
                    mma_tf32(d[fm][fn], af[fm], bf[fn]);
        }
        __syncthreads();
    }

    // ---- Epilogue: each thread owns rows (r, r+8) per fm, 2 cols per fn
#pragma unroll
    for (int fm = 0; fm < 2; fm++) {
        const int nr0 = n0 + warp_n + fm * 16 + qr;
        const int nr1 = nr0 + 8;
        const float bv0 = bias[nr0], bv1 = bias[nr1];
        float *dst0, *dst1;
        if (WHICH == 0) {
            const int t0 = nr0 % 3, c0 = nr0 / 3;
            const int t1 = nr1 % 3, c1 = nr1 / 3;
            float* base0 = (t0 == 0) ? g_Q : ((t0 == 1) ? g_K : g_V);
            float* base1 = (t1 == 0) ? g_Q : ((t1 == 1) ? g_K : g_V);
            dst0 = base0 + (size_t)(b * 256 + c0) * HW_ + m0;
            dst1 = base1 + (size_t)(b * 256 + c1) * HW_ + m0;
        } else {
            dst0 = Y + (size_t)(b * 256 + nr0) * HW_ + m0;
            dst1 = Y + (size_t)(b * 256 + nr1) * HW_ + m0;
        }
#pragma unroll
        for (int fn = 0; fn < 8; fn++) {
            const int col = warp_hw + fn * 8 + qc * 2;
            *(float2*)(dst0 + col) = make_float2(d[fm][fn][0] + bv0, d[fm][fn][1] + bv0);
            *(float2*)(dst1 + col) = make_float2(d[fm][fn][2] + bv1, d[fm][fn][3] + bv1);
        }
    }
}

// ---------------------------------------------------------------------------
// Attention (unchanged from passing R4): one block per (b, head, window).
// ---------------------------------------------------------------------------
__device__ __forceinline__ u64 pack2(float x) {
    u64 r; asm("mov.b64 %0, {%1, %1};" : "=l"(r) : "f"(x)); return r;
}
__device__ __forceinline__ void fma2(u64& acc, u64 a, u64 b) {
    asm("fma.rn.f32x2 %0, %1, %2, %0;" : "+l"(acc) : "l"(a), "l"(b));
}
__device__ __forceinline__ float2 unpack2(u64 v) {
    float2 f; asm("mov.b64 {%0, %1}, %2;" : "=f"(f.x), "=f"(f.y) : "l"(v)); return f;
}

__global__ __launch_bounds__(256) void attn_kernel() {
    extern __shared__ float sm[];
    float* Qs   = sm;                  // [64][34]
    float* Ks   = Qs + 64 * 34;        // [144][34]
    float* Vs   = Ks + 144 * 34;       // [144][34]
    float* Ps   = Vs + 144 * 34;       // [64][146]
    float* isum = Ps + 64 * 146;       // [64]
    float* scratch = Qs;               // reused after scores

    const int win  = blockIdx.x;
    const int wi   = win >> 3, wj = win & 7;
    const int head = blockIdx.y;
    const int b    = blockIdx.z;
    const int tid  = threadIdx.x;
    const int bc   = b * 256 + head * 32;
    const float scale = 0.17677669529663687f;

#pragma unroll
    for (int l = 0; l < 8; l++) {
        int idx = tid + l * 256;
        int e = idx >> 6, p = idx & 63;
        int hw = (wi * 8 + (p >> 3)) * 64 + wj * 8 + (p & 7);
        Qs[p * 34 + e] = g_Q[(size_t)(bc + e) * HW_ + hw] * scale;
    }
    for (int idx = tid; idx < 144 * 32; idx += 256) {
        int e = idx / 144, k = idx - e * 144;
        int pr = k / 12, pc = k - pr * 12;
        int gh = wi * 8 + pr - 2, gw = wj * 8 + pc - 2;
        float kv = 0.f, vv = 0.f;
        if ((unsigned)gh < 64u && (unsigned)gw < 64u) {
            size_t off = (size_t)(bc + e) * HW_ + gh * 64 + gw;
            kv = g_K[off];
            vv = g_V[off];
        }
        Ks[k * 34 + e] = kv;
        Vs[k * 34 + e] = vv;
    }
    __syncthreads();

    {
        const int qg = tid >> 4, kg = tid & 15;
        const float* qbase = Qs + qg * 4 * 34;
        const float* kbase = Ks + kg * 9 * 34;
        u64 acc[4][9];
#pragma unroll
        for (int i = 0; i < 4; i++)
#pragma unroll
            for (int j = 0; j < 9; j++) acc[i][j] = 0ull;
#pragma unroll
        for (int e2 = 0; e2 < 16; e2++) {
            u64 kp[9];
#pragma unroll
            for (int j = 0; j < 9; j++)
                kp[j] = *(const u64*)(kbase + j * 34 + e2 * 2);
#pragma unroll
            for (int i = 0; i < 4; i++) {
                u64 qp = *(const u64*)(qbase + i * 34 + e2 * 2);
#pragma unroll
                for (int j = 0; j < 9; j++) fma2(acc[i][j], qp, kp[j]);
            }
        }
#pragma unroll
        for (int i = 0; i < 4; i++)
#pragma unroll
            for (int j = 0; j < 9; j++) {
                float2 v = unpack2(acc[i][j]);
                Ps[(qg * 4 + i) * 146 + kg * 9 + j] = v.x + v.y;
            }
    }
    __syncthreads();

    {
        const int warp = tid >> 5, lane = tid & 31;
        for (int r = 0; r < 8; r++) {
            int q = warp * 8 + r;
            float m = -1e30f;
            for (int k = lane; k < 144; k += 32) m = fmaxf(m, Ps[q * 146 + k]);
#pragma unroll
            for (int o = 16; o > 0; o >>= 1) m = fmaxf(m, __shfl_xor_sync(0xffffffffu, m, o));
            float s = 0.f;
            for (int k = lane; k < 144; k += 32) {
                float ev = __expf(Ps[q * 146 + k] - m);
                Ps[q * 146 + k] = ev;
                s += ev;
            }
#pragma unroll
            for (int o = 16; o > 0; o >>= 1) s += __shfl_xor_sync(0xffffffffu, s, o);
            if (lane == 0) isum[q] = 1.0f / s;
        }
    }
    __syncthreads();

    const int kh = tid >> 7;
    const int eg = (tid >> 5) & 3;
    const int qp = tid & 31;
    {
        u64 vacc[2][4];
#pragma unroll
        for (int c = 0; c < 4; c++) { vacc[0][c] = 0ull; vacc[1][c] = 0ull; }
        const int kend = kh * 72 + 72;
#pragma unroll 4
        for (int k = kh * 72; k < kend; k++) {
            u64 p0 = pack2(Ps[qp * 146 + k]);
            u64 p1 = pack2(Ps[(qp + 32) * 146 + k]);
            const u64* vrow = (const u64*)(Vs + k * 34 + eg * 8);
#pragma unroll
            for (int c = 0; c < 4; c++) {
                u64 v = vrow[c];
                fma2(vacc[0][c], p0, v);
                fma2(vacc[1][c], p1, v);
            }
        }
        if (kh == 0) {
#pragma unroll
            for (int c = 0; c < 4; c++) {
                float2 v0 = unpack2(vacc[0][c]);
                float2 v1 = unpack2(vacc[1][c]);
                scratch[qp * 32 + eg * 8 + 2 * c]            = v0.x;
                scratch[qp * 32 + eg * 8 + 2 * c + 1]        = v0.y;
                scratch[(qp + 32) * 32 + eg * 8 + 2 * c]     = v1.x;
                scratch[(qp + 32) * 32 + eg * 8 + 2 * c + 1] = v1.y;
            }
        }
        __syncthreads();
        if (kh == 1) {
            const float i0 = isum[qp], i1 = isum[qp + 32];
            const int hw0 = (wi * 8 + (qp >> 3)) * 64 + wj * 8 + (qp & 7);
            const int q1 = qp + 32;
            const int hw1 = (wi * 8 + (q1 >> 3)) * 64 + wj * 8 + (q1 & 7);
#pragma unroll
            for (int c = 0; c < 4; c++) {
                float2 v0 = unpack2(vacc[0][c]);
                float2 v1 = unpack2(vacc[1][c]);
                int e = eg * 8 + 2 * c;
                g_att[(size_t)(bc + e) * HW_ + hw0]     = (v0.x + scratch[qp * 32 + e])     * i0;
                g_att[(size_t)(bc + e + 1) * HW_ + hw0] = (v0.y + scratch[qp * 32 + e + 1]) * i0;
                g_att[(size_t)(bc + e) * HW_ + hw1]     = (v1.x + scratch[q1 * 32 + e])     * i1;
                g_att[(size_t)(bc + e + 1) * HW_ + hw1] = (v1.y + scratch[q1 * 32 + e + 1]) * i1;
            }
        }
    }
}

// ---------------------------------------------------------------------------
extern "C" void kernel_launch(void* const* d_in, const int* in_sizes, int n_in,
                              void* d_out, int out_size) {
    const float* x  = (const float*)d_in[0];
    const float* W1 = (const float*)d_in[1];
    const float* b1 = (const float*)d_in[2];
    const float* W2 = (const float*)d_in[3];
    const float* b2 = (const float*)d_in[4];
    float* y = (float*)d_out;

    const int gemm_smem = 2 * STAGE_FLOATS * 4;   // 73728 bytes
    cudaFuncSetAttribute(gemm_mma<0>, cudaFuncAttributeMaxDynamicSharedMemorySize, gemm_smem);
    cudaFuncSetAttribute(gemm_mma<1>, cudaFuncAttributeMaxDynamicSharedMemorySize, gemm_smem);

    gemm_mma<0><<<dim3(HW_ / 128, 768 / 128, B_), 256, gemm_smem>>>(W1, b1, x, nullptr);

    const size_t attn_smem =
        (size_t)(64 * 34 + 144 * 34 * 2 + 64 * 146 + 64) * sizeof(float);
    cudaFuncSetAttribute(attn_kernel, cudaFuncAttributeMaxDynamicSharedMemorySize,
                         (int)attn_smem);
    attn_kernel<<<dim3(NWIN_ * NWIN_, NH_, B_), 256, attn_smem>>>();

    gemm_mma<1><<<dim3(HW_ / 128, 256 / 128, B_), 256, gemm_smem>>>(W2, b2, nullptr, y);
}